// round 13
// baseline (speedup 1.0000x reference)
#include <cuda_runtime.h>
#include <cuda_bf16.h>
#include <math.h>
#include <stdint.h>

// ---------------- problem constants ----------------
#define BATCH 16
#define IMG   197
#define TXT   24
#define SEQ   222
#define DIM   768
#define NH    12
#define HD    64
#define NL    6
#define VOC   50257
#define FF    3072
#define MROWS (BATCH*SEQ)  // 3552
#define QKVW  (3*DIM)      // 2304
#define MPAD  3584         // 28 * 128
#define NPADV 50432        // 394 * 128

// ---------------- GEMM tiling (tf32 mma.sync + ldmatrix, 3-stage) ----------------
#define TKC    32                 // K per stage (4 k8-steps)
#define ASTRF  36                 // smem row stride in floats -> conflict-free ldmatrix
#define MATSZF (128*ASTRF*4)      // 18432 B per matrix tile
#define STSZ   (2*MATSZF)         // A + B = 36864 B
#define NSTG   3
#define DSMEM  (NSTG*STSZ)        // 110592 B (x2 CTAs = 221184 < 228KB)

// ---------------- device scratch ----------------
__device__ float g_x   [MROWS*DIM];
__device__ float g_qkv [MROWS*QKVW];
__device__ float g_o   [MROWS*DIM];
__device__ float g_t   [MROWS*DIM];
__device__ float g_b   [QKVW];
__device__ float g_a   [MPAD*DIM];           // tf32 activations, K=768 GEMMs
__device__ float g_a2  [MPAD*FF];            // tf32 FFN1 output, K=3072 GEMM
__device__ float g_bt  [(size_t)NPADV*DIM];  // tf32 weights^T [Npad,K]
__device__ float g_logits[(size_t)MROWS*NPADV];

// ---------------- PTX helpers ----------------
__device__ __forceinline__ uint32_t s2u(const void* p) {
    uint32_t a;
    asm("{ .reg .u64 t; cvta.to.shared.u64 t, %1; cvt.u32.u64 %0, t; }" : "=r"(a) : "l"(p));
    return a;
}
#define CP16(dst, src)   asm volatile("cp.async.cg.shared.global [%0], [%1], 16;" :: "r"(dst), "l"(src))
#define CP_COMMIT()      asm volatile("cp.async.commit_group;" ::: "memory")
#define CP_WAIT(n)       asm volatile("cp.async.wait_group %0;" :: "n"(n) : "memory")

__device__ __forceinline__ float tf32r(float v) {
    uint32_t o;
    asm("cvt.rna.tf32.f32 %0, %1;" : "=r"(o) : "f"(v));
    return __uint_as_float(o);
}
__device__ __forceinline__ void mma_tf32(float* c, const uint32_t* a, const uint32_t* b) {
    asm volatile(
        "mma.sync.aligned.m16n8k8.row.col.f32.tf32.tf32.f32 "
        "{%0,%1,%2,%3}, {%4,%5,%6,%7}, {%8,%9}, {%0,%1,%2,%3};"
        : "+f"(c[0]), "+f"(c[1]), "+f"(c[2]), "+f"(c[3])
        : "r"(a[0]), "r"(a[1]), "r"(a[2]), "r"(a[3]), "r"(b[0]), "r"(b[1]));
}
__device__ __forceinline__ void ldsm4(uint32_t* r, uint32_t addr) {
    asm volatile("ldmatrix.sync.aligned.m8n8.x4.shared.b16 {%0,%1,%2,%3}, [%4];"
                 : "=r"(r[0]), "=r"(r[1]), "=r"(r[2]), "=r"(r[3]) : "r"(addr));
}

// ---------------- embedding (writes fp32 x AND tf32 g_a) ----------------
__global__ void embed_kernel(const float* __restrict__ img, const int* __restrict__ tok,
                             const float* __restrict__ temb, const float* __restrict__ sep,
                             float* __restrict__ x, float* __restrict__ ga)
{
    int row = blockIdx.x;
    int b = row / SEQ, s = row % SEQ;
    const float* src;
    if (s < IMG)       src = img + (size_t)(b*IMG + s)*DIM;
    else if (s == IMG) src = sep;
    else               src = temb + (size_t)tok[b*TXT + (s-IMG-1)] * DIM;
    float* dst = x + (size_t)row*DIM;
    float* da  = ga + (size_t)row*DIM;
    for (int i = threadIdx.x; i < DIM; i += blockDim.x) {
        float v = src[i];
        dst[i] = v;
        da[i]  = tf32r(v);
    }
}

// ---------------- weight transpose+round ----------------
__global__ void wt_convert(const float* __restrict__ src, int K, int N)
{
    __shared__ float t[32][33];
    int n0 = blockIdx.x*32, k0 = blockIdx.y*32;
    int tx = threadIdx.x, ty = threadIdx.y;
    #pragma unroll
    for (int j = 0; j < 32; j += 8) {
        int n = n0 + tx;
        t[ty+j][tx] = (n < N) ? src[(size_t)(k0+ty+j)*N + n] : 0.f;
    }
    __syncthreads();
    #pragma unroll
    for (int j = 0; j < 32; j += 8) {
        int n = n0 + ty + j, k = k0 + tx;
        g_bt[(size_t)n*K + k] = tf32r(t[tx][ty+j]);
    }
}

// ---------------- QKV weight gather+round ----------------
__global__ void qkvw_convert(const float* __restrict__ Wq, const float* __restrict__ Wk,
                             const float* __restrict__ Wv,
                             const float* __restrict__ bq, const float* __restrict__ bk,
                             const float* __restrict__ bv)
{
    int idx = blockIdx.x*256 + threadIdx.x;
    if (idx < QKVW*DIM) {
        int c = idx / DIM, d = idx % DIM;
        int which = c / DIM, w2 = c % DIM;
        int h = w2 >> 6, e = w2 & 63;
        const float* W = (which == 0) ? Wq : (which == 1) ? Wk : Wv;
        g_bt[idx] = tf32r(W[(size_t)h*DIM*HD + (size_t)d*HD + e]);
    }
    if (idx < QKVW) {
        int which = idx / DIM, cc = idx % DIM;
        const float* bb = (which == 0) ? bq : (which == 1) ? bk : bv;
        g_b[idx] = bb[cc];
    }
}

// ---------------- tf32 mma.sync GEMM, 3-stage cp.async, ldmatrix frags ----------------
__global__ __launch_bounds__(256, 2)
void gemm_mma(const float* __restrict__ Aa, const float* __restrict__ Bt,
              const float* __restrict__ bias, float* __restrict__ C,
              int K, int ldc, int Nreal, int Mreal, int relu, int tf32out)
{
    extern __shared__ char dsm[];
    const int tid = threadIdx.x;
    const int wid = tid >> 5, lane = tid & 31;
    const int m0 = blockIdx.x * 128, n0 = blockIdx.y * 128;
    const int wm = wid >> 2, wn = wid & 3;
    const int g = lane >> 2, t = lane & 3;
    const int nk = K / TKC;
    const uint32_t sb = s2u(dsm);

    const uint32_t aLaneOff =
        (uint32_t)(((wm*64 + ((lane & 8) ? 8 : 0) + (lane & 7)) * ASTRF)
                   + ((lane & 16) ? 4 : 0)) * 4;
    const uint32_t bLaneOff =
        (uint32_t)(((wn*32 + ((lane & 16) ? 8 : 0) + (lane & 7)) * ASTRF)
                   + ((lane & 8) ? 4 : 0)) * 4;

    float acc[4][4][4];
    #pragma unroll
    for (int mi = 0; mi < 4; mi++)
        #pragma unroll
        for (int ni = 0; ni < 4; ni++)
            #pragma unroll
            for (int r = 0; r < 4; r++) acc[mi][ni][r] = 0.f;

    #define LOAD_ST(st, kc) do {                                                     \
        int k0_ = (kc) * TKC;                                                        \
        _Pragma("unroll")                                                            \
        for (int c_ = tid; c_ < 2048; c_ += 256) {                                   \
            int isB_ = (c_ >= 1024);                                                 \
            int cc_  = c_ & 1023;                                                    \
            int row_ = cc_ >> 3, c4_ = cc_ & 7;                                      \
            const float* sp_ = (isB_ ? Bt + (size_t)(n0 + row_) * K                  \
                                     : Aa + (size_t)(m0 + row_) * K) + k0_ + c4_*4;  \
            uint32_t dst_ = sb + (st)*STSZ + (isB_ ? MATSZF : 0) + row_*144 + c4_*16;\
            CP16(dst_, sp_);                                                         \
        }                                                                            \
        CP_COMMIT();                                                                 \
    } while (0)

    LOAD_ST(0, 0);
    LOAD_ST(1, 1);

    int cur = 0, nx2 = 2;
    for (int kc = 0; kc < nk; kc++) {
        if (kc < nk - 1) CP_WAIT(1); else CP_WAIT(0);
        __syncthreads();
        if (kc + 2 < nk) LOAD_ST(nx2, kc + 2);

        const uint32_t stg = sb + cur*STSZ;
        const uint32_t aB = stg + aLaneOff;
        const uint32_t bB = stg + MATSZF + bLaneOff;

        #pragma unroll
        for (int ks = 0; ks < 4; ks++) {
            const uint32_t kof = ks * 32;
            uint32_t af[16], bf[16];
            #pragma unroll
            for (int mi = 0; mi < 4; mi++)
                ldsm4(af + mi*4, aB + mi*(16*ASTRF*4) + kof);
            ldsm4(bf,     bB + kof);
            ldsm4(bf + 4, bB + 16*ASTRF*4 + kof);
            #pragma unroll
            for (int mi = 0; mi < 4; mi++) {
                #pragma unroll
                for (int ni = 0; ni < 4; ni++)
                    mma_tf32(acc[mi][ni], af + mi*4, bf + ni*2);
            }
        }
        cur = (cur == 2) ? 0 : cur + 1;
        nx2 = (nx2 == 2) ? 0 : nx2 + 1;
    }

    #pragma unroll
    for (int mi = 0; mi < 4; mi++) {
        int gm0 = m0 + wm*64 + mi*16 + g;
        #pragma unroll
        for (int ni = 0; ni < 4; ni++) {
            int gn = n0 + wn*32 + ni*8 + t*2;
            float bx = (gn     < Nreal) ? bias[gn]     : 0.f;
            float by = (gn + 1 < Nreal) ? bias[gn + 1] : 0.f;
            float c0 = acc[mi][ni][0] + bx, c1 = acc[mi][ni][1] + by;
            float c2 = acc[mi][ni][2] + bx, c3 = acc[mi][ni][3] + by;
            if (relu) {
                c0 = fmaxf(c0, 0.f); c1 = fmaxf(c1, 0.f);
                c2 = fmaxf(c2, 0.f); c3 = fmaxf(c3, 0.f);
            }
            if (tf32out) {
                c0 = tf32r(c0); c1 = tf32r(c1); c2 = tf32r(c2); c3 = tf32r(c3);
            }
            if (gm0 < Mreal)
                *reinterpret_cast<float2*>(C + (size_t)gm0*ldc + gn) = make_float2(c0, c1);
            if (gm0 + 8 < Mreal)
                *reinterpret_cast<float2*>(C + (size_t)(gm0+8)*ldc + gn) = make_float2(c2, c3);
        }
    }
}

// ---------------- attention: 1 block per (b,h), 512 thr, 2 CTAs/SM ----------------
// K in smem (stride 65); V streamed from global (coalesced, L1-resident 57KB block).
// Smem ~76KB -> 2 CTAs/SM -> 32 warps resident (R12 was latency-bound at 16).
#define KSTR 65
#define AW   16
__global__ __launch_bounds__(512, 2)
void attn_kernel(const float* __restrict__ qkv,
                 const int* __restrict__ tmask,
                 float* __restrict__ o)
{
    int b = blockIdx.x / NH, h = blockIdx.x % NH;
    extern __shared__ float sm[];
    float* ks = sm;                         // SEQ*65
    float* qs = ks + SEQ*KSTR;              // AW*64
    float* sc = qs + AW*64;                 // AW*224
    unsigned char* valid = (unsigned char*)(sc + AW*224);

    int tid = threadIdx.x, lane = tid & 31, w = tid >> 5;
    const float* base = qkv + (size_t)b * SEQ * QKVW;
    const float* vbase = base + 2*DIM + h*64;

    for (int i = tid; i < SEQ*HD; i += 512) {
        int t = i >> 6, e = i & 63;
        ks[t*KSTR + e] = base[(size_t)t*QKVW + DIM + h*64 + e];
    }
    for (int t = tid; t < SEQ; t += 512)
        valid[t] = (t < SEQ - TXT) ? 1 : (tmask[b*TXT + t - (SEQ-TXT)] != 0);
    __syncthreads();

    float* myq  = qs + w*64;
    float* mysc = sc + w*224;
    for (int s = w; s < SEQ; s += AW) {
        myq[lane]      = base[(size_t)s*QKVW + h*64 + lane];
        myq[lane + 32] = base[(size_t)s*QKVW + h*64 + lane + 32];
        __syncwarp();

        float lmax = -INFINITY;
        for (int t = lane; t <= s; t += 32) {
            float d = -INFINITY;
            if (valid[t]) {
                d = 0.f;
                #pragma unroll
                for (int e = 0; e < 64; e++) d += myq[e] * ks[t*KSTR + e];
                d *= 0.125f;
            }
            mysc[t] = d;
            lmax = fmaxf(lmax, d);
        }
        #pragma unroll
        for (int off = 16; off; off >>= 1)
            lmax = fmaxf(lmax, __shfl_xor_sync(0xffffffffu, lmax, off));

        float lsum = 0.f;
        for (int t = lane; t <= s; t += 32) {
            float p = expf(mysc[t] - lmax);
            mysc[t] = p;
            lsum += p;
        }
        #pragma unroll
        for (int off = 16; off; off >>= 1)
            lsum += __shfl_xor_sync(0xffffffffu, lsum, off);
        float inv = 1.f / lsum;
        __syncwarp();

        float acc0 = 0.f, acc1 = 0.f;
        for (int t = 0; t <= s; t++) {
            float p = mysc[t];
            const float* vr = vbase + (size_t)t*QKVW;
            acc0 += p * vr[lane];
            acc1 += p * vr[lane + 32];
        }
        float* orow = o + (size_t)(b*SEQ + s)*DIM + h*64;
        orow[lane]      = acc0 * inv;
        orow[lane + 32] = acc1 * inv;
        __syncwarp();
    }
}
#define ATTN_SMEM ((SEQ*KSTR + AW*64 + AW*224) * 4 + 256)

// ---------------- residual add + LayerNorm (writes fp32 out AND tf32 ga) ----------------
__global__ void add_ln_kernel(const float* __restrict__ x, const float* __restrict__ r,
                              const float* __restrict__ sc, const float* __restrict__ bi,
                              float* __restrict__ out, float* __restrict__ ga)
{
    __shared__ float buf[DIM];
    __shared__ float red1[8], red2[8];
    int row = blockIdx.x, tid = threadIdx.x, lane = tid & 31, w = tid >> 5;
    const float* xr = x + (size_t)row*DIM;
    const float* rr = r + (size_t)row*DIM;

    float s = 0.f;
    for (int i = tid; i < DIM; i += 256) { float v = xr[i] + rr[i]; buf[i] = v; s += v; }
    #pragma unroll
    for (int off = 16; off; off >>= 1) s += __shfl_xor_sync(0xffffffffu, s, off);
    if (lane == 0) red1[w] = s;
    __syncthreads();
    float tot = 0.f;
    #pragma unroll
    for (int i = 0; i < 8; i++) tot += red1[i];
    float mu = tot * (1.f / DIM);

    float vsum = 0.f;
    for (int i = tid; i < DIM; i += 256) { float d = buf[i] - mu; vsum += d*d; }
    #pragma unroll
    for (int off = 16; off; off >>= 1) vsum += __shfl_xor_sync(0xffffffffu, vsum, off);
    if (lane == 0) red2[w] = vsum;
    __syncthreads();
    float vtot = 0.f;
    #pragma unroll
    for (int i = 0; i < 8; i++) vtot += red2[i];
    float inv = rsqrtf(vtot * (1.f / DIM) + 1e-5f);

    float* orow = out + (size_t)row*DIM;
    float* arow = ga  + (size_t)row*DIM;
    for (int i = tid; i < DIM; i += 256) {
        float v = (buf[i] - mu) * inv * sc[i] + bi[i];
        orow[i] = v;
        arow[i] = tf32r(v);
    }
}

// ---------------- softmax: padded logits -> d_out ----------------
__global__ void softmax_rows(const float* __restrict__ in, float* __restrict__ out)
{
    int row = blockIdx.x, tid = threadIdx.x, lane = tid & 31, w = tid >> 5;
    const float* p = in + (size_t)row * NPADV;
    float* q = out + (size_t)row * VOC;
    __shared__ float smm[8], sss[8];

    float m = -INFINITY, s = 0.f;
    for (int i = tid; i < VOC; i += 256) {
        float xv = p[i];
        if (xv > m) { s = s * expf(m - xv) + 1.f; m = xv; }
        else        { s += expf(xv - m); }
    }
    #pragma unroll
    for (int off = 16; off; off >>= 1) {
        float m2 = __shfl_xor_sync(0xffffffffu, m, off);
        float s2 = __shfl_xor_sync(0xffffffffu, s, off);
        float mn = fmaxf(m, m2);
        s = s * expf(m - mn) + s2 * expf(m2 - mn);
        m = mn;
    }
    if (lane == 0) { smm[w] = m; sss[w] = s; }
    __syncthreads();
    if (tid == 0) {
        float M = smm[0], Sv = sss[0];
        #pragma unroll
        for (int i = 1; i < 8; i++) {
            float m2 = smm[i], s2 = sss[i];
            float mn = fmaxf(M, m2);
            Sv = Sv * expf(M - mn) + s2 * expf(m2 - mn);
            M = mn;
        }
        smm[0] = M; sss[0] = 1.f / Sv;
    }
    __syncthreads();
    float M = smm[0], inv = sss[0];
    for (int i = tid; i < VOC; i += 256)
        q[i] = expf(p[i] - M) * inv;
}

// ---------------- host driver ----------------
extern "C" void kernel_launch(void* const* d_in, const int* in_sizes, int n_in,
                              void* d_out, int out_size)
{
    const float* img   = (const float*)d_in[0];
    const int*   tok   = (const int*)  d_in[1];
    const int*   tmask = (const int*)  d_in[2];
    const float* temb  = (const float*)d_in[3];
    const float* sep   = (const float*)d_in[4];
    const float* Wq    = (const float*)d_in[5];
    const float* bq    = (const float*)d_in[6];
    const float* Wk    = (const float*)d_in[7];
    const float* bk    = (const float*)d_in[8];
    const float* Wv    = (const float*)d_in[9];
    const float* bv    = (const float*)d_in[10];
    const float* ln1s  = (const float*)d_in[11];
    const float* ln1b  = (const float*)d_in[12];
    const float* W1    = (const float*)d_in[13];
    const float* b1    = (const float*)d_in[14];
    const float* W2    = (const float*)d_in[15];
    const float* b2    = (const float*)d_in[16];
    const float* ln2s  = (const float*)d_in[17];
    const float* ln2b  = (const float*)d_in[18];
    const float* Wout  = (const float*)d_in[19];
    const float* bout  = (const float*)d_in[20];
    float* out = (float*)d_out;

    float *px, *pqkv, *po, *pt, *pb, *plog, *pa, *pa2, *pbt;
    cudaGetSymbolAddress((void**)&px,   g_x);
    cudaGetSymbolAddress((void**)&pqkv, g_qkv);
    cudaGetSymbolAddress((void**)&po,   g_o);
    cudaGetSymbolAddress((void**)&pt,   g_t);
    cudaGetSymbolAddress((void**)&pb,   g_b);
    cudaGetSymbolAddress((void**)&plog, g_logits);
    cudaGetSymbolAddress((void**)&pa,   g_a);
    cudaGetSymbolAddress((void**)&pa2,  g_a2);
    cudaGetSymbolAddress((void**)&pbt,  g_bt);

    cudaFuncSetAttribute(attn_kernel, cudaFuncAttributeMaxDynamicSharedMemorySize, ATTN_SMEM);
    cudaFuncSetAttribute(gemm_mma, cudaFuncAttributeMaxDynamicSharedMemorySize, DSMEM);

    embed_kernel<<<MROWS, 256>>>(img, tok, temb, sep, px, pa);

    #define GEMM(A, bias, C, K, ldc, Nreal, Npad, relu, tfo) \
        gemm_mma<<<dim3(MPAD/128, (Npad)/128), 256, DSMEM>>>(A, pbt, bias, C, K, ldc, Nreal, MROWS, relu, tfo)

    for (int l = 0; l < NL; l++) {
        const size_t woff = (size_t)l * NH * DIM * HD;
        // QKV  (A = g_a, written by embed / previous add_ln2)
        qkvw_convert<<<(QKVW*DIM + 255)/256, 256>>>(Wq + woff, Wk + woff, Wv + woff,
                                                    bq + (size_t)l*DIM, bk + (size_t)l*DIM,
                                                    bv + (size_t)l*DIM);
        GEMM(pa, pb, pqkv, DIM, QKVW, QKVW, QKVW, 0, 0);
        attn_kernel<<<BATCH*NH, 512, ATTN_SMEM>>>(pqkv, tmask, po);
        add_ln_kernel<<<MROWS, 256>>>(px, po, ln1s + (size_t)l*DIM, ln1b + (size_t)l*DIM, px, pa);
        // FFN1: writes tf32 relu output directly to g_a2
        wt_convert<<<dim3(FF/32, DIM/32), dim3(32, 8)>>>(W1 + (size_t)l*DIM*FF, DIM, FF);
        GEMM(pa, b1 + (size_t)l*FF, pa2, DIM, FF, FF, FF, 1, 1);
        // FFN2 (A = g_a2)
        wt_convert<<<dim3(DIM/32, FF/32), dim3(32, 8)>>>(W2 + (size_t)l*FF*DIM, FF, DIM);
        GEMM(pa2, b2 + (size_t)l*DIM, pt, FF, DIM, DIM, DIM, 0, 0);
        add_ln_kernel<<<MROWS, 256>>>(px, pt, ln2s + (size_t)l*DIM, ln2b + (size_t)l*DIM, px, pa);
    }

    // vocab projection (padded logits) + softmax into d_out
    wt_convert<<<dim3(NPADV/32, DIM/32), dim3(32, 8)>>>(Wout, DIM, VOC);
    GEMM(pa, bout, plog, DIM, NPADV, VOC, NPADV, 0, 0);
    softmax_rows<<<MROWS, 256>>>(plog, out);
}

// round 14
// speedup vs baseline: 1.0991x; 1.0991x over previous
#include <cuda_runtime.h>
#include <cuda_bf16.h>
#include <math.h>
#include <stdint.h>

// ---------------- problem constants ----------------
#define BATCH 16
#define IMG   197
#define TXT   24
#define SEQ   222
#define DIM   768
#define NH    12
#define HD    64
#define NL    6
#define VOC   50257
#define FF    3072
#define MROWS (BATCH*SEQ)  // 3552
#define QKVW  (3*DIM)      // 2304
#define MPAD  3584         // 28 * 128
#define NPADV 50432        // 394 * 128
#define NBH   (BATCH*NH)   // 192

// ---------------- GEMM tiling (tf32 mma.sync + ldmatrix, 3-stage) ----------------
#define TKC    32                 // K per stage (4 k8-steps)
#define ASTRF  36                 // smem row stride in floats -> conflict-free ldmatrix
#define MATSZF (128*ASTRF*4)      // 18432 B per matrix tile
#define STSZ   (2*MATSZF)         // A + B = 36864 B
#define NSTG   3
#define DSMEM  (NSTG*STSZ)        // 110592 B (x2 CTAs = 221184 < 228KB)

// ---------------- attention scratch dims ----------------
#define AQROWS 256                // padded seq rows for qt/kt/S
#define VROWS  128                // padded head-dim rows for vt
#define VCOLS  224                // padded t cols for vt / P (7 * TKC)
#define SLD    256                // S row stride

// ---------------- device scratch ----------------
__device__ float g_x   [MROWS*DIM];
__device__ float g_qkv [MROWS*QKVW];
__device__ float g_o   [MROWS*DIM];
__device__ float g_t   [MROWS*DIM];
__device__ float g_b   [QKVW];
__device__ float g_a   [MPAD*DIM];
__device__ float g_a2  [MPAD*FF];
__device__ float g_bt  [(size_t)NPADV*DIM];
__device__ float g_logits[(size_t)MROWS*NPADV];
__device__ float g_qt  [(size_t)NBH*AQROWS*HD];
__device__ float g_kt  [(size_t)NBH*AQROWS*HD];
__device__ float g_vt  [(size_t)NBH*VROWS*VCOLS];
__device__ float g_s   [(size_t)NBH*AQROWS*SLD];

// ---------------- PTX helpers ----------------
__device__ __forceinline__ uint32_t s2u(const void* p) {
    uint32_t a;
    asm("{ .reg .u64 t; cvta.to.shared.u64 t, %1; cvt.u32.u64 %0, t; }" : "=r"(a) : "l"(p));
    return a;
}
#define CP16(dst, src)   asm volatile("cp.async.cg.shared.global [%0], [%1], 16;" :: "r"(dst), "l"(src))
#define CP_COMMIT()      asm volatile("cp.async.commit_group;" ::: "memory")
#define CP_WAIT(n)       asm volatile("cp.async.wait_group %0;" :: "n"(n) : "memory")

__device__ __forceinline__ float tf32r(float v) {
    uint32_t o;
    asm("cvt.rna.tf32.f32 %0, %1;" : "=r"(o) : "f"(v));
    return __uint_as_float(o);
}
__device__ __forceinline__ void mma_tf32(float* c, const uint32_t* a, const uint32_t* b) {
    asm volatile(
        "mma.sync.aligned.m16n8k8.row.col.f32.tf32.tf32.f32 "
        "{%0,%1,%2,%3}, {%4,%5,%6,%7}, {%8,%9}, {%0,%1,%2,%3};"
        : "+f"(c[0]), "+f"(c[1]), "+f"(c[2]), "+f"(c[3])
        : "r"(a[0]), "r"(a[1]), "r"(a[2]), "r"(a[3]), "r"(b[0]), "r"(b[1]));
}
__device__ __forceinline__ void ldsm4(uint32_t* r, uint32_t addr) {
    asm volatile("ldmatrix.sync.aligned.m8n8.x4.shared.b16 {%0,%1,%2,%3}, [%4];"
                 : "=r"(r[0]), "=r"(r[1]), "=r"(r[2]), "=r"(r[3]) : "r"(addr));
}

// ---------------- embedding (writes fp32 x AND tf32 g_a) ----------------
__global__ void embed_kernel(const float* __restrict__ img, const int* __restrict__ tok,
                             const float* __restrict__ temb, const float* __restrict__ sep,
                             float* __restrict__ x, float* __restrict__ ga)
{
    int row = blockIdx.x;
    int b = row / SEQ, s = row % SEQ;
    const float* src;
    if (s < IMG)       src = img + (size_t)(b*IMG + s)*DIM;
    else if (s == IMG) src = sep;
    else               src = temb + (size_t)tok[b*TXT + (s-IMG-1)] * DIM;
    float* dst = x + (size_t)row*DIM;
    float* da  = ga + (size_t)row*DIM;
    for (int i = threadIdx.x; i < DIM; i += blockDim.x) {
        float v = src[i];
        dst[i] = v;
        da[i]  = tf32r(v);
    }
}

// ---------------- weight transpose+round ----------------
__global__ void wt_convert(const float* __restrict__ src, int K, int N)
{
    __shared__ float t[32][33];
    int n0 = blockIdx.x*32, k0 = blockIdx.y*32;
    int tx = threadIdx.x, ty = threadIdx.y;
    #pragma unroll
    for (int j = 0; j < 32; j += 8) {
        int n = n0 + tx;
        t[ty+j][tx] = (n < N) ? src[(size_t)(k0+ty+j)*N + n] : 0.f;
    }
    __syncthreads();
    #pragma unroll
    for (int j = 0; j < 32; j += 8) {
        int n = n0 + ty + j, k = k0 + tx;
        g_bt[(size_t)n*K + k] = tf32r(t[tx][ty+j]);
    }
}

// ---------------- QKV weight gather+round ----------------
__global__ void qkvw_convert(const float* __restrict__ Wq, const float* __restrict__ Wk,
                             const float* __restrict__ Wv,
                             const float* __restrict__ bq, const float* __restrict__ bk,
                             const float* __restrict__ bv)
{
    int idx = blockIdx.x*256 + threadIdx.x;
    if (idx < QKVW*DIM) {
        int c = idx / DIM, d = idx % DIM;
        int which = c / DIM, w2 = c % DIM;
        int h = w2 >> 6, e = w2 & 63;
        const float* W = (which == 0) ? Wq : (which == 1) ? Wk : Wv;
        g_bt[idx] = tf32r(W[(size_t)h*DIM*HD + (size_t)d*HD + e]);
    }
    if (idx < QKVW) {
        int which = idx / DIM, cc = idx % DIM;
        const float* bb = (which == 0) ? bq : (which == 1) ? bk : bv;
        g_b[idx] = bb[cc];
    }
}

// ---------------- tf32 mma.sync GEMM, 3-stage cp.async, ldmatrix frags ----------------
__global__ __launch_bounds__(256, 2)
void gemm_mma(const float* __restrict__ Aa, const float* __restrict__ Bt,
              const float* __restrict__ bias, float* __restrict__ C,
              int K, int ldc, int Nreal, int Mreal, int relu, int tf32out)
{
    extern __shared__ char dsm[];
    const int tid = threadIdx.x;
    const int wid = tid >> 5, lane = tid & 31;
    const int m0 = blockIdx.x * 128, n0 = blockIdx.y * 128;
    const int wm = wid >> 2, wn = wid & 3;
    const int g = lane >> 2, t = lane & 3;
    const int nk = K / TKC;
    const uint32_t sb = s2u(dsm);

    const uint32_t aLaneOff =
        (uint32_t)(((wm*64 + ((lane & 8) ? 8 : 0) + (lane & 7)) * ASTRF)
                   + ((lane & 16) ? 4 : 0)) * 4;
    const uint32_t bLaneOff =
        (uint32_t)(((wn*32 + ((lane & 16) ? 8 : 0) + (lane & 7)) * ASTRF)
                   + ((lane & 8) ? 4 : 0)) * 4;

    float acc[4][4][4];
    #pragma unroll
    for (int mi = 0; mi < 4; mi++)
        #pragma unroll
        for (int ni = 0; ni < 4; ni++)
            #pragma unroll
            for (int r = 0; r < 4; r++) acc[mi][ni][r] = 0.f;

    #define LOAD_ST(st, kc) do {                                                     \
        int k0_ = (kc) * TKC;                                                        \
        _Pragma("unroll")                                                            \
        for (int c_ = tid; c_ < 2048; c_ += 256) {                                   \
            int isB_ = (c_ >= 1024);                                                 \
            int cc_  = c_ & 1023;                                                    \
            int row_ = cc_ >> 3, c4_ = cc_ & 7;                                      \
            const float* sp_ = (isB_ ? Bt + (size_t)(n0 + row_) * K                  \
                                     : Aa + (size_t)(m0 + row_) * K) + k0_ + c4_*4;  \
            uint32_t dst_ = sb + (st)*STSZ + (isB_ ? MATSZF : 0) + row_*144 + c4_*16;\
            CP16(dst_, sp_);                                                         \
        }                                                                            \
        CP_COMMIT();                                                                 \
    } while (0)

    LOAD_ST(0, 0);
    LOAD_ST(1, 1);

    int cur = 0, nx2 = 2;
    for (int kc = 0; kc < nk; kc++) {
        if (kc < nk - 1) CP_WAIT(1); else CP_WAIT(0);
        __syncthreads();
        if (kc + 2 < nk) LOAD_ST(nx2, kc + 2);

        const uint32_t stg = sb + cur*STSZ;
        const uint32_t aB = stg + aLaneOff;
        const uint32_t bB = stg + MATSZF + bLaneOff;

        #pragma unroll
        for (int ks = 0; ks < 4; ks++) {
            const uint32_t kof = ks * 32;
            uint32_t af[16], bf[16];
            #pragma unroll
            for (int mi = 0; mi < 4; mi++)
                ldsm4(af + mi*4, aB + mi*(16*ASTRF*4) + kof);
            ldsm4(bf,     bB + kof);
            ldsm4(bf + 4, bB + 16*ASTRF*4 + kof);
            #pragma unroll
            for (int mi = 0; mi < 4; mi++) {
                #pragma unroll
                for (int ni = 0; ni < 4; ni++)
                    mma_tf32(acc[mi][ni], af + mi*4, bf + ni*2);
            }
        }
        cur = (cur == 2) ? 0 : cur + 1;
        nx2 = (nx2 == 2) ? 0 : nx2 + 1;
    }

    #pragma unroll
    for (int mi = 0; mi < 4; mi++) {
        int gm0 = m0 + wm*64 + mi*16 + g;
        #pragma unroll
        for (int ni = 0; ni < 4; ni++) {
            int gn = n0 + wn*32 + ni*8 + t*2;
            float bx = (gn     < Nreal) ? bias[gn]     : 0.f;
            float by = (gn + 1 < Nreal) ? bias[gn + 1] : 0.f;
            float c0 = acc[mi][ni][0] + bx, c1 = acc[mi][ni][1] + by;
            float c2 = acc[mi][ni][2] + bx, c3 = acc[mi][ni][3] + by;
            if (relu) {
                c0 = fmaxf(c0, 0.f); c1 = fmaxf(c1, 0.f);
                c2 = fmaxf(c2, 0.f); c3 = fmaxf(c3, 0.f);
            }
            if (tf32out) {
                c0 = tf32r(c0); c1 = tf32r(c1); c2 = tf32r(c2); c3 = tf32r(c3);
            }
            if (gm0 < Mreal)
                *reinterpret_cast<float2*>(C + (size_t)gm0*ldc + gn) = make_float2(c0, c1);
            if (gm0 + 8 < Mreal)
                *reinterpret_cast<float2*>(C + (size_t)(gm0+8)*ldc + gn) = make_float2(c2, c3);
        }
    }
}

// ---------------- batched tf32 GEMM for attention (blockIdx.z = bh) ----------------
// C[M,N] = A[M,K(lda)] * Bt[N,K(ldb)]^T ; stores guarded by Mreal/Nreal.
__global__ __launch_bounds__(256, 2)
void attn_gemm(const float* __restrict__ Ab, const float* __restrict__ Btb,
               float* __restrict__ Cb,
               int K, int lda, int ldb, int ldc, int Mreal, int Nreal,
               size_t sA, size_t sB, size_t sCb, size_t sCh)
{
    extern __shared__ char dsm[];
    const int bh = blockIdx.z;
    const float* Aa = Ab  + sA*bh;
    const float* Bt = Btb + sB*bh;
    float* C = Cb + sCb*(size_t)(bh/NH) + sCh*(size_t)(bh%NH);

    const int tid = threadIdx.x;
    const int wid = tid >> 5, lane = tid & 31;
    const int m0 = blockIdx.x * 128, n0 = blockIdx.y * 128;
    const int wm = wid >> 2, wn = wid & 3;
    const int g = lane >> 2, t = lane & 3;
    const int nk = K / TKC;
    const uint32_t sb = s2u(dsm);

    const uint32_t aLaneOff =
        (uint32_t)(((wm*64 + ((lane & 8) ? 8 : 0) + (lane & 7)) * ASTRF)
                   + ((lane & 16) ? 4 : 0)) * 4;
    const uint32_t bLaneOff =
        (uint32_t)(((wn*32 + ((lane & 16) ? 8 : 0) + (lane & 7)) * ASTRF)
                   + ((lane & 8) ? 4 : 0)) * 4;

    float acc[4][4][4];
    #pragma unroll
    for (int mi = 0; mi < 4; mi++)
        #pragma unroll
        for (int ni = 0; ni < 4; ni++)
            #pragma unroll
            for (int r = 0; r < 4; r++) acc[mi][ni][r] = 0.f;

    #define LOAD_ST2(st, kc) do {                                                    \
        int k0_ = (kc) * TKC;                                                        \
        _Pragma("unroll")                                                            \
        for (int c_ = tid; c_ < 2048; c_ += 256) {                                   \
            int isB_ = (c_ >= 1024);                                                 \
            int cc_  = c_ & 1023;                                                    \
            int row_ = cc_ >> 3, c4_ = cc_ & 7;                                      \
            const float* sp_ = (isB_ ? Bt + (size_t)(n0 + row_) * ldb                \
                                     : Aa + (size_t)(m0 + row_) * lda) + k0_ + c4_*4;\
            uint32_t dst_ = sb + (st)*STSZ + (isB_ ? MATSZF : 0) + row_*144 + c4_*16;\
            CP16(dst_, sp_);                                                         \
        }                                                                            \
        CP_COMMIT();                                                                 \
    } while (0)

    LOAD_ST2(0, 0);
    LOAD_ST2(1, 1);

    int cur = 0, nx2 = 2;
    for (int kc = 0; kc < nk; kc++) {
        if (kc < nk - 1) CP_WAIT(1); else CP_WAIT(0);
        __syncthreads();
        if (kc + 2 < nk) LOAD_ST2(nx2, kc + 2);

        const uint32_t stg = sb + cur*STSZ;
        const uint32_t aB = stg + aLaneOff;
        const uint32_t bB = stg + MATSZF + bLaneOff;

        #pragma unroll
        for (int ks = 0; ks < 4; ks++) {
            const uint32_t kof = ks * 32;
            uint32_t af[16], bf[16];
            #pragma unroll
            for (int mi = 0; mi < 4; mi++)
                ldsm4(af + mi*4, aB + mi*(16*ASTRF*4) + kof);
            ldsm4(bf,     bB + kof);
            ldsm4(bf + 4, bB + 16*ASTRF*4 + kof);
            #pragma unroll
            for (int mi = 0; mi < 4; mi++) {
                #pragma unroll
                for (int ni = 0; ni < 4; ni++)
                    mma_tf32(acc[mi][ni], af + mi*4, bf + ni*2);
            }
        }
        cur = (cur == 2) ? 0 : cur + 1;
        nx2 = (nx2 == 2) ? 0 : nx2 + 1;
    }

    #pragma unroll
    for (int mi = 0; mi < 4; mi++) {
        int gm0 = m0 + wm*64 + mi*16 + g;
        #pragma unroll
        for (int ni = 0; ni < 4; ni++) {
            int gn = n0 + wn*32 + ni*8 + t*2;
            if (gn >= Nreal) continue;
            if (gm0 < Mreal)
                *reinterpret_cast<float2*>(C + (size_t)gm0*ldc + gn) =
                    make_float2(acc[mi][ni][0], acc[mi][ni][1]);
            if (gm0 + 8 < Mreal)
                *reinterpret_cast<float2*>(C + (size_t)(gm0+8)*ldc + gn) =
                    make_float2(acc[mi][ni][2], acc[mi][ni][3]);
        }
    }
}

// ---------------- attention repack: qkv -> qt/kt (tf32 [256x64]) + vt^T ([128x224]) ----
__global__ void repack_qkv(const float* __restrict__ qkv)
{
    int bh = blockIdx.x;
    int b = bh / NH, h = bh % NH;
    const float* base = qkv + (size_t)b*SEQ*QKVW + h*64;
    float* qt = g_qt + (size_t)bh*AQROWS*HD;
    float* kt = g_kt + (size_t)bh*AQROWS*HD;
    float* vt = g_vt + (size_t)bh*VROWS*VCOLS;
    for (int i = threadIdx.x; i < SEQ*HD; i += 256) {
        int s = i >> 6, e = i & 63;
        const float* src = base + (size_t)s*QKVW;
        qt[i] = tf32r(src[e]);
        kt[i] = tf32r(src[DIM + e]);
        vt[e*VCOLS + s] = tf32r(src[2*DIM + e]);
    }
}

// ---------------- attention masked softmax over S rows (warp per row) ----------------
__global__ void attn_softmax(const int* __restrict__ tmask)
{
    int bh = blockIdx.y, b = bh / NH;
    int s = blockIdx.x*8 + (threadIdx.x >> 5);
    int lane = threadIdx.x & 31;
    if (s >= SEQ) return;
    float* row = g_s + ((size_t)bh*AQROWS + s)*SLD;

    float x[7];
    float m = -INFINITY;
    #pragma unroll
    for (int j = 0; j < 7; j++) {
        int t = lane + 32*j;
        bool val = (t <= s) && (t < SEQ) &&
                   (t < SEQ-TXT || tmask[b*TXT + t - (SEQ-TXT)] != 0);
        x[j] = val ? row[t]*0.125f : -INFINITY;
        m = fmaxf(m, x[j]);
    }
    #pragma unroll
    for (int off = 16; off; off >>= 1)
        m = fmaxf(m, __shfl_xor_sync(0xffffffffu, m, off));

    float sum = 0.f;
    #pragma unroll
    for (int j = 0; j < 7; j++) { x[j] = expf(x[j] - m); sum += x[j]; }
    #pragma unroll
    for (int off = 16; off; off >>= 1)
        sum += __shfl_xor_sync(0xffffffffu, sum, off);
    float inv = 1.f / sum;

    #pragma unroll
    for (int j = 0; j < 7; j++)
        row[lane + 32*j] = tf32r(x[j] * inv);
}

// ---------------- residual add + LayerNorm (writes fp32 out AND tf32 ga) ----------------
__global__ void add_ln_kernel(const float* __restrict__ x, const float* __restrict__ r,
                              const float* __restrict__ sc, const float* __restrict__ bi,
                              float* __restrict__ out, float* __restrict__ ga)
{
    __shared__ float buf[DIM];
    __shared__ float red1[8], red2[8];
    int row = blockIdx.x, tid = threadIdx.x, lane = tid & 31, w = tid >> 5;
    const float* xr = x + (size_t)row*DIM;
    const float* rr = r + (size_t)row*DIM;

    float s = 0.f;
    for (int i = tid; i < DIM; i += 256) { float v = xr[i] + rr[i]; buf[i] = v; s += v; }
    #pragma unroll
    for (int off = 16; off; off >>= 1) s += __shfl_xor_sync(0xffffffffu, s, off);
    if (lane == 0) red1[w] = s;
    __syncthreads();
    float tot = 0.f;
    #pragma unroll
    for (int i = 0; i < 8; i++) tot += red1[i];
    float mu = tot * (1.f / DIM);

    float vsum = 0.f;
    for (int i = tid; i < DIM; i += 256) { float d = buf[i] - mu; vsum += d*d; }
    #pragma unroll
    for (int off = 16; off; off >>= 1) vsum += __shfl_xor_sync(0xffffffffu, vsum, off);
    if (lane == 0) red2[w] = vsum;
    __syncthreads();
    float vtot = 0.f;
    #pragma unroll
    for (int i = 0; i < 8; i++) vtot += red2[i];
    float inv = rsqrtf(vtot * (1.f / DIM) + 1e-5f);

    float* orow = out + (size_t)row*DIM;
    float* arow = ga  + (size_t)row*DIM;
    for (int i = tid; i < DIM; i += 256) {
        float v = (buf[i] - mu) * inv * sc[i] + bi[i];
        orow[i] = v;
        arow[i] = tf32r(v);
    }
}

// ---------------- softmax: padded logits -> d_out ----------------
__global__ void softmax_rows(const float* __restrict__ in, float* __restrict__ out)
{
    int row = blockIdx.x, tid = threadIdx.x, lane = tid & 31, w = tid >> 5;
    const float* p = in + (size_t)row * NPADV;
    float* q = out + (size_t)row * VOC;
    __shared__ float smm[8], sss[8];

    float m = -INFINITY, s = 0.f;
    for (int i = tid; i < VOC; i += 256) {
        float xv = p[i];
        if (xv > m) { s = s * expf(m - xv) + 1.f; m = xv; }
        else        { s += expf(xv - m); }
    }
    #pragma unroll
    for (int off = 16; off; off >>= 1) {
        float m2 = __shfl_xor_sync(0xffffffffu, m, off);
        float s2 = __shfl_xor_sync(0xffffffffu, s, off);
        float mn = fmaxf(m, m2);
        s = s * expf(m - mn) + s2 * expf(m2 - mn);
        m = mn;
    }
    if (lane == 0) { smm[w] = m; sss[w] = s; }
    __syncthreads();
    if (tid == 0) {
        float M = smm[0], Sv = sss[0];
        #pragma unroll
        for (int i = 1; i < 8; i++) {
            float m2 = smm[i], s2 = sss[i];
            float mn = fmaxf(M, m2);
            Sv = Sv * expf(M - mn) + s2 * expf(m2 - mn);
            M = mn;
        }
        smm[0] = M; sss[0] = 1.f / Sv;
    }
    __syncthreads();
    float M = smm[0], inv = sss[0];
    for (int i = tid; i < VOC; i += 256)
        q[i] = expf(p[i] - M) * inv;
}

// ---------------- host driver ----------------
extern "C" void kernel_launch(void* const* d_in, const int* in_sizes, int n_in,
                              void* d_out, int out_size)
{
    const float* img   = (const float*)d_in[0];
    const int*   tok   = (const int*)  d_in[1];
    const int*   tmask = (const int*)  d_in[2];
    const float* temb  = (const float*)d_in[3];
    const float* sep   = (const float*)d_in[4];
    const float* Wq    = (const float*)d_in[5];
    const float* bq    = (const float*)d_in[6];
    const float* Wk    = (const float*)d_in[7];
    const float* bk    = (const float*)d_in[8];
    const float* Wv    = (const float*)d_in[9];
    const float* bv    = (const float*)d_in[10];
    const float* ln1s  = (const float*)d_in[11];
    const float* ln1b  = (const float*)d_in[12];
    const float* W1    = (const float*)d_in[13];
    const float* b1    = (const float*)d_in[14];
    const float* W2    = (const float*)d_in[15];
    const float* b2    = (const float*)d_in[16];
    const float* ln2s  = (const float*)d_in[17];
    const float* ln2b  = (const float*)d_in[18];
    const float* Wout  = (const float*)d_in[19];
    const float* bout  = (const float*)d_in[20];
    float* out = (float*)d_out;

    float *px, *pqkv, *po, *pt, *pb, *plog, *pa, *pa2, *pbt;
    float *pqt, *pkt, *pvt, *ps;
    cudaGetSymbolAddress((void**)&px,   g_x);
    cudaGetSymbolAddress((void**)&pqkv, g_qkv);
    cudaGetSymbolAddress((void**)&po,   g_o);
    cudaGetSymbolAddress((void**)&pt,   g_t);
    cudaGetSymbolAddress((void**)&pb,   g_b);
    cudaGetSymbolAddress((void**)&plog, g_logits);
    cudaGetSymbolAddress((void**)&pa,   g_a);
    cudaGetSymbolAddress((void**)&pa2,  g_a2);
    cudaGetSymbolAddress((void**)&pbt,  g_bt);
    cudaGetSymbolAddress((void**)&pqt,  g_qt);
    cudaGetSymbolAddress((void**)&pkt,  g_kt);
    cudaGetSymbolAddress((void**)&pvt,  g_vt);
    cudaGetSymbolAddress((void**)&ps,   g_s);

    cudaFuncSetAttribute(gemm_mma,  cudaFuncAttributeMaxDynamicSharedMemorySize, DSMEM);
    cudaFuncSetAttribute(attn_gemm, cudaFuncAttributeMaxDynamicSharedMemorySize, DSMEM);

    embed_kernel<<<MROWS, 256>>>(img, tok, temb, sep, px, pa);

    #define GEMM(A, bias, C, K, ldc, Nreal, Npad, relu, tfo) \
        gemm_mma<<<dim3(MPAD/128, (Npad)/128), 256, DSMEM>>>(A, pbt, bias, C, K, ldc, Nreal, MROWS, relu, tfo)

    for (int l = 0; l < NL; l++) {
        const size_t woff = (size_t)l * NH * DIM * HD;
        // QKV projection
        qkvw_convert<<<(QKVW*DIM + 255)/256, 256>>>(Wq + woff, Wk + woff, Wv + woff,
                                                    bq + (size_t)l*DIM, bk + (size_t)l*DIM,
                                                    bv + (size_t)l*DIM);
        GEMM(pa, pb, pqkv, DIM, QKVW, QKVW, QKVW, 0, 0);
        // attention: repack -> S = Q K^T -> softmax -> O = P V (direct into g_o)
        repack_qkv<<<NBH, 256>>>(pqkv);
        attn_gemm<<<dim3(2, 2, NBH), 256, DSMEM>>>(
            pqt, pkt, ps, HD, HD, HD, SLD, SEQ, SLD,
            (size_t)AQROWS*HD, (size_t)AQROWS*HD,
            (size_t)NH*AQROWS*SLD, (size_t)AQROWS*SLD);
        attn_softmax<<<dim3(28, NBH), 256>>>(tmask);
        attn_gemm<<<dim3(2, 1, NBH), 256, DSMEM>>>(
            ps, pvt, po, VCOLS, SLD, VCOLS, DIM, SEQ, HD,
            (size_t)AQROWS*SLD, (size_t)VROWS*VCOLS,
            (size_t)SEQ*DIM, (size_t)HD);
        add_ln_kernel<<<MROWS, 256>>>(px, po, ln1s + (size_t)l*DIM, ln1b + (size_t)l*DIM, px, pa);
        // FFN1 (tf32 relu output straight to g_a2)
        wt_convert<<<dim3(FF/32, DIM/32), dim3(32, 8)>>>(W1 + (size_t)l*DIM*FF, DIM, FF);
        GEMM(pa, b1 + (size_t)l*FF, pa2, DIM, FF, FF, FF, 1, 1);
        // FFN2
        wt_convert<<<dim3(DIM/32, FF/32), dim3(32, 8)>>>(W2 + (size_t)l*FF*DIM, FF, DIM);
        GEMM(pa2, b2 + (size_t)l*DIM, pt, FF, DIM, DIM, DIM, 0, 0);
        add_ln_kernel<<<MROWS, 256>>>(px, pt, ln2s + (size_t)l*DIM, ln2b + (size_t)l*DIM, px, pa);
    }

    // vocab projection (padded logits) + softmax into d_out
    wt_convert<<<dim3(NPADV/32, DIM/32), dim3(32, 8)>>>(Wout, DIM, VOC);
    GEMM(pa, bout, plog, DIM, NPADV, VOC, NPADV, 0, 0);
    softmax_rows<<<MROWS, 256>>>(plog, out);
}

// round 15
// speedup vs baseline: 1.1374x; 1.0348x over previous
#include <cuda_runtime.h>
#include <cuda_bf16.h>
#include <math.h>
#include <stdint.h>

// ---------------- problem constants ----------------
#define BATCH 16
#define IMG   197
#define TXT   24
#define SEQ   222
#define DIM   768
#define NH    12
#define HD    64
#define NL    6
#define VOC   50257
#define FF    3072
#define MROWS (BATCH*SEQ)  // 3552
#define QKVW  (3*DIM)      // 2304
#define MPAD  3584         // 28 * 128
#define NPADV 50432        // 394 * 128
#define NBH   (BATCH*NH)   // 192

// ---------------- GEMM tiling (tf32 mma.sync + ldmatrix, 3-stage) ----------------
#define TKC    32
#define ASTRF  36
#define MATSZF (128*ASTRF*4)
#define STSZ   (2*MATSZF)
#define NSTG   3
#define DSMEM  (NSTG*STSZ)

// ---------------- attention scratch dims ----------------
#define AQROWS 256
#define VROWS  128
#define VCOLS  224
#define SLD    256

// ---------------- device scratch ----------------
__device__ float g_x   [MROWS*DIM];
__device__ float g_o   [MROWS*DIM];
__device__ float g_t   [MROWS*DIM];
__device__ float g_b   [QKVW];
__device__ float g_a   [MPAD*DIM];
__device__ float g_a2  [MPAD*FF];
__device__ float g_bt  [(size_t)NPADV*DIM];
__device__ float g_logits[(size_t)MROWS*NPADV];
__device__ float g_qt  [(size_t)NBH*AQROWS*HD];
__device__ float g_kt  [(size_t)NBH*AQROWS*HD];
__device__ float g_vt  [(size_t)NBH*VROWS*VCOLS];
__device__ float g_s   [(size_t)NBH*AQROWS*SLD];

// ---------------- PTX helpers ----------------
__device__ __forceinline__ uint32_t s2u(const void* p) {
    uint32_t a;
    asm("{ .reg .u64 t; cvta.to.shared.u64 t, %1; cvt.u32.u64 %0, t; }" : "=r"(a) : "l"(p));
    return a;
}
#define CP16(dst, src)   asm volatile("cp.async.cg.shared.global [%0], [%1], 16;" :: "r"(dst), "l"(src))
#define CP_COMMIT()      asm volatile("cp.async.commit_group;" ::: "memory")
#define CP_WAIT(n)       asm volatile("cp.async.wait_group %0;" :: "n"(n) : "memory")

__device__ __forceinline__ float tf32r(float v) {
    uint32_t o;
    asm("cvt.rna.tf32.f32 %0, %1;" : "=r"(o) : "f"(v));
    return __uint_as_float(o);
}
__device__ __forceinline__ void mma_tf32(float* c, const uint32_t* a, const uint32_t* b) {
    asm volatile(
        "mma.sync.aligned.m16n8k8.row.col.f32.tf32.tf32.f32 "
        "{%0,%1,%2,%3}, {%4,%5,%6,%7}, {%8,%9}, {%0,%1,%2,%3};"
        : "+f"(c[0]), "+f"(c[1]), "+f"(c[2]), "+f"(c[3])
        : "r"(a[0]), "r"(a[1]), "r"(a[2]), "r"(a[3]), "r"(b[0]), "r"(b[1]));
}
__device__ __forceinline__ void ldsm4(uint32_t* r, uint32_t addr) {
    asm volatile("ldmatrix.sync.aligned.m8n8.x4.shared.b16 {%0,%1,%2,%3}, [%4];"
                 : "=r"(r[0]), "=r"(r[1]), "=r"(r[2]), "=r"(r[3]) : "r"(addr));
}

// ---------------- embedding (writes fp32 x AND tf32 g_a) ----------------
__global__ void embed_kernel(const float* __restrict__ img, const int* __restrict__ tok,
                             const float* __restrict__ temb, const float* __restrict__ sep,
                             float* __restrict__ x, float* __restrict__ ga)
{
    int row = blockIdx.x;
    int b = row / SEQ, s = row % SEQ;
    const float* src;
    if (s < IMG)       src = img + (size_t)(b*IMG + s)*DIM;
    else if (s == IMG) src = sep;
    else               src = temb + (size_t)tok[b*TXT + (s-IMG-1)] * DIM;
    float* dst = x + (size_t)row*DIM;
    float* da  = ga + (size_t)row*DIM;
    for (int i = threadIdx.x; i < DIM; i += blockDim.x) {
        float v = src[i];
        dst[i] = v;
        da[i]  = tf32r(v);
    }
}

// ---------------- weight transpose+round ----------------
__global__ void wt_convert(const float* __restrict__ src, int K, int N)
{
    __shared__ float t[32][33];
    int n0 = blockIdx.x*32, k0 = blockIdx.y*32;
    int tx = threadIdx.x, ty = threadIdx.y;
    #pragma unroll
    for (int j = 0; j < 32; j += 8) {
        int n = n0 + tx;
        t[ty+j][tx] = (n < N) ? src[(size_t)(k0+ty+j)*N + n] : 0.f;
    }
    __syncthreads();
    #pragma unroll
    for (int j = 0; j < 32; j += 8) {
        int n = n0 + ty + j, k = k0 + tx;
        g_bt[(size_t)n*K + k] = tf32r(t[tx][ty+j]);
    }
}

// ---------------- QKV weight gather+round ----------------
__global__ void qkvw_convert(const float* __restrict__ Wq, const float* __restrict__ Wk,
                             const float* __restrict__ Wv,
                             const float* __restrict__ bq, const float* __restrict__ bk,
                             const float* __restrict__ bv)
{
    int idx = blockIdx.x*256 + threadIdx.x;
    if (idx < QKVW*DIM) {
        int c = idx / DIM, d = idx % DIM;
        int which = c / DIM, w2 = c % DIM;
        int h = w2 >> 6, e = w2 & 63;
        const float* W = (which == 0) ? Wq : (which == 1) ? Wk : Wv;
        g_bt[idx] = tf32r(W[(size_t)h*DIM*HD + (size_t)d*HD + e]);
    }
    if (idx < QKVW) {
        int which = idx / DIM, cc = idx % DIM;
        const float* bb = (which == 0) ? bq : (which == 1) ? bk : bv;
        g_b[idx] = bb[cc];
    }
}

// ---------------- tf32 mma.sync GEMM, 3-stage cp.async, ldmatrix frags ----------------
// qkvmode: epilogue scatters tf32(acc+bias) directly into g_qt / g_kt / g_vt (no C).
__global__ __launch_bounds__(256, 2)
void gemm_mma(const float* __restrict__ Aa, const float* __restrict__ Bt,
              const float* __restrict__ bias, float* __restrict__ C,
              int K, int ldc, int Nreal, int Mreal, int relu, int tf32out, int qkvmode)
{
    extern __shared__ char dsm[];
    const int tid = threadIdx.x;
    const int wid = tid >> 5, lane = tid & 31;
    const int m0 = blockIdx.x * 128, n0 = blockIdx.y * 128;
    const int wm = wid >> 2, wn = wid & 3;
    const int g = lane >> 2, t = lane & 3;
    const int nk = K / TKC;
    const uint32_t sb = s2u(dsm);

    const uint32_t aLaneOff =
        (uint32_t)(((wm*64 + ((lane & 8) ? 8 : 0) + (lane & 7)) * ASTRF)
                   + ((lane & 16) ? 4 : 0)) * 4;
    const uint32_t bLaneOff =
        (uint32_t)(((wn*32 + ((lane & 16) ? 8 : 0) + (lane & 7)) * ASTRF)
                   + ((lane & 8) ? 4 : 0)) * 4;

    float acc[4][4][4];
    #pragma unroll
    for (int mi = 0; mi < 4; mi++)
        #pragma unroll
        for (int ni = 0; ni < 4; ni++)
            #pragma unroll
            for (int r = 0; r < 4; r++) acc[mi][ni][r] = 0.f;

    #define LOAD_ST(st, kc) do {                                                     \
        int k0_ = (kc) * TKC;                                                        \
        _Pragma("unroll")                                                            \
        for (int c_ = tid; c_ < 2048; c_ += 256) {                                   \
            int isB_ = (c_ >= 1024);                                                 \
            int cc_  = c_ & 1023;                                                    \
            int row_ = cc_ >> 3, c4_ = cc_ & 7;                                      \
            const float* sp_ = (isB_ ? Bt + (size_t)(n0 + row_) * K                  \
                                     : Aa + (size_t)(m0 + row_) * K) + k0_ + c4_*4;  \
            uint32_t dst_ = sb + (st)*STSZ + (isB_ ? MATSZF : 0) + row_*144 + c4_*16;\
            CP16(dst_, sp_);                                                         \
        }                                                                            \
        CP_COMMIT();                                                                 \
    } while (0)

    LOAD_ST(0, 0);
    LOAD_ST(1, 1);

    int cur = 0, nx2 = 2;
    for (int kc = 0; kc < nk; kc++) {
        if (kc < nk - 1) CP_WAIT(1); else CP_WAIT(0);
        __syncthreads();
        if (kc + 2 < nk) LOAD_ST(nx2, kc + 2);

        const uint32_t stg = sb + cur*STSZ;
        const uint32_t aB = stg + aLaneOff;
        const uint32_t bB = stg + MATSZF + bLaneOff;

        #pragma unroll
        for (int ks = 0; ks < 4; ks++) {
            const uint32_t kof = ks * 32;
            uint32_t af[16], bf[16];
            #pragma unroll
            for (int mi = 0; mi < 4; mi++)
                ldsm4(af + mi*4, aB + mi*(16*ASTRF*4) + kof);
            ldsm4(bf,     bB + kof);
            ldsm4(bf + 4, bB + 16*ASTRF*4 + kof);
            #pragma unroll
            for (int mi = 0; mi < 4; mi++) {
                #pragma unroll
                for (int ni = 0; ni < 4; ni++)
                    mma_tf32(acc[mi][ni], af + mi*4, bf + ni*2);
            }
        }
        cur = (cur == 2) ? 0 : cur + 1;
        nx2 = (nx2 == 2) ? 0 : nx2 + 1;
    }

    if (qkvmode) {
        // scatter epilogue: columns [0,768)->Q, [768,1536)->K, [1536,2304)->V^T
        #pragma unroll
        for (int mi = 0; mi < 4; mi++) {
            #pragma unroll
            for (int rr = 0; rr < 2; rr++) {
                int gm = m0 + wm*64 + mi*16 + g + rr*8;
                if (gm >= Mreal) continue;
                int b = gm / SEQ, s = gm - b*SEQ;
                #pragma unroll
                for (int ni = 0; ni < 4; ni++) {
                    int gn = n0 + wn*32 + ni*8 + t*2;
                    float v0 = tf32r(acc[mi][ni][rr*2+0] + bias[gn]);
                    float v1 = tf32r(acc[mi][ni][rr*2+1] + bias[gn+1]);
                    int which = gn / DIM;
                    int w2 = gn - which*DIM;
                    int h = w2 >> 6, e = w2 & 63;
                    size_t bh = (size_t)(b*NH + h);
                    if (which == 0) {
                        *reinterpret_cast<float2*>(&g_qt[bh*AQROWS*HD + (size_t)s*HD + e]) =
                            make_float2(v0, v1);
                    } else if (which == 1) {
                        *reinterpret_cast<float2*>(&g_kt[bh*AQROWS*HD + (size_t)s*HD + e]) =
                            make_float2(v0, v1);
                    } else {
                        g_vt[bh*VROWS*VCOLS + (size_t)e*VCOLS + s]     = v0;
                        g_vt[bh*VROWS*VCOLS + (size_t)(e+1)*VCOLS + s] = v1;
                    }
                }
            }
        }
        return;
    }

    #pragma unroll
    for (int mi = 0; mi < 4; mi++) {
        int gm0 = m0 + wm*64 + mi*16 + g;
        #pragma unroll
        for (int ni = 0; ni < 4; ni++) {
            int gn = n0 + wn*32 + ni*8 + t*2;
            float bx = (gn     < Nreal) ? bias[gn]     : 0.f;
            float by = (gn + 1 < Nreal) ? bias[gn + 1] : 0.f;
            float c0 = acc[mi][ni][0] + bx, c1 = acc[mi][ni][1] + by;
            float c2 = acc[mi][ni][2] + bx, c3 = acc[mi][ni][3] + by;
            if (relu) {
                c0 = fmaxf(c0, 0.f); c1 = fmaxf(c1, 0.f);
                c2 = fmaxf(c2, 0.f); c3 = fmaxf(c3, 0.f);
            }
            if (tf32out) {
                c0 = tf32r(c0); c1 = tf32r(c1); c2 = tf32r(c2); c3 = tf32r(c3);
            }
            if (gm0 < Mreal)
                *reinterpret_cast<float2*>(C + (size_t)gm0*ldc + gn) = make_float2(c0, c1);
            if (gm0 + 8 < Mreal)
                *reinterpret_cast<float2*>(C + (size_t)(gm0+8)*ldc + gn) = make_float2(c2, c3);
        }
    }
}

// ---------------- batched tf32 GEMM for attention (blockIdx.z = bh) ----------------
__global__ __launch_bounds__(256, 2)
void attn_gemm(const float* __restrict__ Ab, const float* __restrict__ Btb,
               float* __restrict__ Cb,
               int K, int lda, int ldb, int ldc, int Mreal, int Nreal,
               size_t sA, size_t sB, size_t sCb, size_t sCh)
{
    extern __shared__ char dsm[];
    const int bh = blockIdx.z;
    const float* Aa = Ab  + sA*bh;
    const float* Bt = Btb + sB*bh;
    float* C = Cb + sCb*(size_t)(bh/NH) + sCh*(size_t)(bh%NH);

    const int tid = threadIdx.x;
    const int wid = tid >> 5, lane = tid & 31;
    const int m0 = blockIdx.x * 128, n0 = blockIdx.y * 128;
    const int wm = wid >> 2, wn = wid & 3;
    const int g = lane >> 2, t = lane & 3;
    const int nk = K / TKC;
    const uint32_t sb = s2u(dsm);

    const uint32_t aLaneOff =
        (uint32_t)(((wm*64 + ((lane & 8) ? 8 : 0) + (lane & 7)) * ASTRF)
                   + ((lane & 16) ? 4 : 0)) * 4;
    const uint32_t bLaneOff =
        (uint32_t)(((wn*32 + ((lane & 16) ? 8 : 0) + (lane & 7)) * ASTRF)
                   + ((lane & 8) ? 4 : 0)) * 4;

    float acc[4][4][4];
    #pragma unroll
    for (int mi = 0; mi < 4; mi++)
        #pragma unroll
        for (int ni = 0; ni < 4; ni++)
            #pragma unroll
            for (int r = 0; r < 4; r++) acc[mi][ni][r] = 0.f;

    #define LOAD_ST2(st, kc) do {                                                    \
        int k0_ = (kc) * TKC;                                                        \
        _Pragma("unroll")                                                            \
        for (int c_ = tid; c_ < 2048; c_ += 256) {                                   \
            int isB_ = (c_ >= 1024);                                                 \
            int cc_  = c_ & 1023;                                                    \
            int row_ = cc_ >> 3, c4_ = cc_ & 7;                                      \
            const float* sp_ = (isB_ ? Bt + (size_t)(n0 + row_) * ldb                \
                                     : Aa + (size_t)(m0 + row_) * lda) + k0_ + c4_*4;\
            uint32_t dst_ = sb + (st)*STSZ + (isB_ ? MATSZF : 0) + row_*144 + c4_*16;\
            CP16(dst_, sp_);                                                         \
        }                                                                            \
        CP_COMMIT();                                                                 \
    } while (0)

    LOAD_ST2(0, 0);
    LOAD_ST2(1, 1);

    int cur = 0, nx2 = 2;
    for (int kc = 0; kc < nk; kc++) {
        if (kc < nk - 1) CP_WAIT(1); else CP_WAIT(0);
        __syncthreads();
        if (kc + 2 < nk) LOAD_ST2(nx2, kc + 2);

        const uint32_t stg = sb + cur*STSZ;
        const uint32_t aB = stg + aLaneOff;
        const uint32_t bB = stg + MATSZF + bLaneOff;

        #pragma unroll
        for (int ks = 0; ks < 4; ks++) {
            const uint32_t kof = ks * 32;
            uint32_t af[16], bf[16];
            #pragma unroll
            for (int mi = 0; mi < 4; mi++)
                ldsm4(af + mi*4, aB + mi*(16*ASTRF*4) + kof);
            ldsm4(bf,     bB + kof);
            ldsm4(bf + 4, bB + 16*ASTRF*4 + kof);
            #pragma unroll
            for (int mi = 0; mi < 4; mi++) {
                #pragma unroll
                for (int ni = 0; ni < 4; ni++)
                    mma_tf32(acc[mi][ni], af + mi*4, bf + ni*2);
            }
        }
        cur = (cur == 2) ? 0 : cur + 1;
        nx2 = (nx2 == 2) ? 0 : nx2 + 1;
    }

    #pragma unroll
    for (int mi = 0; mi < 4; mi++) {
        int gm0 = m0 + wm*64 + mi*16 + g;
        #pragma unroll
        for (int ni = 0; ni < 4; ni++) {
            int gn = n0 + wn*32 + ni*8 + t*2;
            if (gn >= Nreal) continue;
            if (gm0 < Mreal)
                *reinterpret_cast<float2*>(C + (size_t)gm0*ldc + gn) =
                    make_float2(acc[mi][ni][0], acc[mi][ni][1]);
            if (gm0 + 8 < Mreal)
                *reinterpret_cast<float2*>(C + (size_t)(gm0+8)*ldc + gn) =
                    make_float2(acc[mi][ni][2], acc[mi][ni][3]);
        }
    }
}

// ---------------- attention masked softmax over S rows (warp per row) ----------------
__global__ void attn_softmax(const int* __restrict__ tmask)
{
    int bh = blockIdx.y, b = bh / NH;
    int s = blockIdx.x*8 + (threadIdx.x >> 5);
    int lane = threadIdx.x & 31;
    if (s >= SEQ) return;
    float* row = g_s + ((size_t)bh*AQROWS + s)*SLD;

    float x[7];
    float m = -INFINITY;
    #pragma unroll
    for (int j = 0; j < 7; j++) {
        int t = lane + 32*j;
        bool val = (t <= s) && (t < SEQ) &&
                   (t < SEQ-TXT || tmask[b*TXT + t - (SEQ-TXT)] != 0);
        x[j] = val ? row[t]*0.125f : -INFINITY;
        m = fmaxf(m, x[j]);
    }
    #pragma unroll
    for (int off = 16; off; off >>= 1)
        m = fmaxf(m, __shfl_xor_sync(0xffffffffu, m, off));

    float sum = 0.f;
    #pragma unroll
    for (int j = 0; j < 7; j++) { x[j] = expf(x[j] - m); sum += x[j]; }
    #pragma unroll
    for (int off = 16; off; off >>= 1)
        sum += __shfl_xor_sync(0xffffffffu, sum, off);
    float inv = 1.f / sum;

    #pragma unroll
    for (int j = 0; j < 7; j++)
        row[lane + 32*j] = tf32r(x[j] * inv);
}

// ---------------- residual add + LayerNorm (writes fp32 out AND tf32 ga) ----------------
__global__ void add_ln_kernel(const float* __restrict__ x, const float* __restrict__ r,
                              const float* __restrict__ sc, const float* __restrict__ bi,
                              float* __restrict__ out, float* __restrict__ ga)
{
    __shared__ float buf[DIM];
    __shared__ float red1[8], red2[8];
    int row = blockIdx.x, tid = threadIdx.x, lane = tid & 31, w = tid >> 5;
    const float* xr = x + (size_t)row*DIM;
    const float* rr = r + (size_t)row*DIM;

    float s = 0.f;
    for (int i = tid; i < DIM; i += 256) { float v = xr[i] + rr[i]; buf[i] = v; s += v; }
    #pragma unroll
    for (int off = 16; off; off >>= 1) s += __shfl_xor_sync(0xffffffffu, s, off);
    if (lane == 0) red1[w] = s;
    __syncthreads();
    float tot = 0.f;
    #pragma unroll
    for (int i = 0; i < 8; i++) tot += red1[i];
    float mu = tot * (1.f / DIM);

    float vsum = 0.f;
    for (int i = tid; i < DIM; i += 256) { float d = buf[i] - mu; vsum += d*d; }
    #pragma unroll
    for (int off = 16; off; off >>= 1) vsum += __shfl_xor_sync(0xffffffffu, vsum, off);
    if (lane == 0) red2[w] = vsum;
    __syncthreads();
    float vtot = 0.f;
    #pragma unroll
    for (int i = 0; i < 8; i++) vtot += red2[i];
    float inv = rsqrtf(vtot * (1.f / DIM) + 1e-5f);

    float* orow = out + (size_t)row*DIM;
    float* arow = ga  + (size_t)row*DIM;
    for (int i = tid; i < DIM; i += 256) {
        float v = (buf[i] - mu) * inv * sc[i] + bi[i];
        orow[i] = v;
        arow[i] = tf32r(v);
    }
}

// ---------------- softmax: padded logits -> d_out ----------------
__global__ void softmax_rows(const float* __restrict__ in, float* __restrict__ out)
{
    int row = blockIdx.x, tid = threadIdx.x, lane = tid & 31, w = tid >> 5;
    const float* p = in + (size_t)row * NPADV;
    float* q = out + (size_t)row * VOC;
    __shared__ float smm[8], sss[8];

    float m = -INFINITY, s = 0.f;
    for (int i = tid; i < VOC; i += 256) {
        float xv = p[i];
        if (xv > m) { s = s * expf(m - xv) + 1.f; m = xv; }
        else        { s += expf(xv - m); }
    }
    #pragma unroll
    for (int off = 16; off; off >>= 1) {
        float m2 = __shfl_xor_sync(0xffffffffu, m, off);
        float s2 = __shfl_xor_sync(0xffffffffu, s, off);
        float mn = fmaxf(m, m2);
        s = s * expf(m - mn) + s2 * expf(m2 - mn);
        m = mn;
    }
    if (lane == 0) { smm[w] = m; sss[w] = s; }
    __syncthreads();
    if (tid == 0) {
        float M = smm[0], Sv = sss[0];
        #pragma unroll
        for (int i = 1; i < 8; i++) {
            float m2 = smm[i], s2 = sss[i];
            float mn = fmaxf(M, m2);
            Sv = Sv * expf(M - mn) + s2 * expf(m2 - mn);
            M = mn;
        }
        smm[0] = M; sss[0] = 1.f / Sv;
    }
    __syncthreads();
    float M = smm[0], inv = sss[0];
    for (int i = tid; i < VOC; i += 256)
        q[i] = expf(p[i] - M) * inv;
}

// ---------------- host driver ----------------
extern "C" void kernel_launch(void* const* d_in, const int* in_sizes, int n_in,
                              void* d_out, int out_size)
{
    const float* img   = (const float*)d_in[0];
    const int*   tok   = (const int*)  d_in[1];
    const int*   tmask = (const int*)  d_in[2];
    const float* temb  = (const float*)d_in[3];
    const float* sep   = (const float*)d_in[4];
    const float* Wq    = (const float*)d_in[5];
    const float* bq    = (const float*)d_in[6];
    const float* Wk    = (const float*)d_in[7];
    const float* bk    = (const float*)d_in[8];
    const float* Wv    = (const float*)d_in[9];
    const float* bv    = (const float*)d_in[10];
    const float* ln1s  = (const float*)d_in[11];
    const float* ln1b  = (const float*)d_in[12];
    const float* W1    = (const float*)d_in[13];
    const float* b1    = (const float*)d_in[14];
    const float* W2    = (const float*)d_in[15];
    const float* b2    = (const float*)d_in[16];
    const float* ln2s  = (const float*)d_in[17];
    const float* ln2b  = (const float*)d_in[18];
    const float* Wout  = (const float*)d_in[19];
    const float* bout  = (const float*)d_in[20];
    float* out = (float*)d_out;

    float *px, *po, *pt, *pb, *plog, *pa, *pa2, *pbt;
    float *pqt, *pkt, *pvt, *ps;
    cudaGetSymbolAddress((void**)&px,   g_x);
    cudaGetSymbolAddress((void**)&po,   g_o);
    cudaGetSymbolAddress((void**)&pt,   g_t);
    cudaGetSymbolAddress((void**)&pb,   g_b);
    cudaGetSymbolAddress((void**)&plog, g_logits);
    cudaGetSymbolAddress((void**)&pa,   g_a);
    cudaGetSymbolAddress((void**)&pa2,  g_a2);
    cudaGetSymbolAddress((void**)&pbt,  g_bt);
    cudaGetSymbolAddress((void**)&pqt,  g_qt);
    cudaGetSymbolAddress((void**)&pkt,  g_kt);
    cudaGetSymbolAddress((void**)&pvt,  g_vt);
    cudaGetSymbolAddress((void**)&ps,   g_s);

    cudaFuncSetAttribute(gemm_mma,  cudaFuncAttributeMaxDynamicSharedMemorySize, DSMEM);
    cudaFuncSetAttribute(attn_gemm, cudaFuncAttributeMaxDynamicSharedMemorySize, DSMEM);

    embed_kernel<<<MROWS, 256>>>(img, tok, temb, sep, px, pa);

    #define GEMM(A, bias, C, K, ldc, Nreal, Npad, relu, tfo, qkvm) \
        gemm_mma<<<dim3(MPAD/128, (Npad)/128), 256, DSMEM>>>(A, pbt, bias, C, K, ldc, Nreal, MROWS, relu, tfo, qkvm)

    for (int l = 0; l < NL; l++) {
        const size_t woff = (size_t)l * NH * DIM * HD;
        // QKV projection with scatter epilogue -> g_qt / g_kt / g_vt directly
        qkvw_convert<<<(QKVW*DIM + 255)/256, 256>>>(Wq + woff, Wk + woff, Wv + woff,
                                                    bq + (size_t)l*DIM, bk + (size_t)l*DIM,
                                                    bv + (size_t)l*DIM);
        GEMM(pa, pb, (float*)nullptr, DIM, QKVW, QKVW, QKVW, 0, 0, 1);
        // attention: S = Q K^T -> softmax -> O = P V (direct into g_o)
        attn_gemm<<<dim3(2, 2, NBH), 256, DSMEM>>>(
            pqt, pkt, ps, HD, HD, HD, SLD, SEQ, SLD,
            (size_t)AQROWS*HD, (size_t)AQROWS*HD,
            (size_t)NH*AQROWS*SLD, (size_t)AQROWS*SLD);
        attn_softmax<<<dim3(28, NBH), 256>>>(tmask);
        attn_gemm<<<dim3(2, 1, NBH), 256, DSMEM>>>(
            ps, pvt, po, VCOLS, SLD, VCOLS, DIM, SEQ, HD,
            (size_t)AQROWS*SLD, (size_t)VROWS*VCOLS,
            (size_t)SEQ*DIM, (size_t)HD);
        add_ln_kernel<<<MROWS, 256>>>(px, po, ln1s + (size_t)l*DIM, ln1b + (size_t)l*DIM, px, pa);
        // FFN1 (tf32 relu output straight to g_a2)
        wt_convert<<<dim3(FF/32, DIM/32), dim3(32, 8)>>>(W1 + (size_t)l*DIM*FF, DIM, FF);
        GEMM(pa, b1 + (size_t)l*FF, pa2, DIM, FF, FF, FF, 1, 1, 0);
        // FFN2
        wt_convert<<<dim3(DIM/32, FF/32), dim3(32, 8)>>>(W2 + (size_t)l*FF*DIM, FF, DIM);
        GEMM(pa2, b2 + (size_t)l*DIM, pt, FF, DIM, DIM, DIM, 0, 0, 0);
        add_ln_kernel<<<MROWS, 256>>>(px, pt, ln2s + (size_t)l*DIM, ln2b + (size_t)l*DIM, px, pa);
    }

    // vocab projection (padded logits) + softmax into d_out
    wt_convert<<<dim3(NPADV/32, DIM/32), dim3(32, 8)>>>(Wout, DIM, VOC);
    GEMM(pa, bout, plog, DIM, NPADV, VOC, NPADV, 0, 0, 0);
    softmax_rows<<<MROWS, 256>>>(plog, out);
}